// round 1
// baseline (speedup 1.0000x reference)
#include <cuda_runtime.h>
#include <cuda_bf16.h>
#include <math.h>

// Problem constants
#define BB 4
#define LL 64
#define DD 64
#define RELN 16
#define NEGV (-1e9f)

// ---------------- scratch (__device__ globals; no allocation) ----------------
__device__ float g_o[BB * LL * DD];                 // embeddings o[b][l][d]
__device__ float g_v[BB * RELN * LL * DD];          // v[b][k][j][d] = sum_e M_k[d,e]*o[b][j][e]
__device__ float g_gx[BB * LL * 3 * DD];            // GRU input projections
__device__ float g_hseq[BB * LL * DD];              // GRU outputs

// ---------------- KA: embedding gather + relation matvec precompute ----------
// grid = 64 blocks: b = blk>>4, k = blk&15; 256 threads
__global__ void ka_embed_relmat(const int* __restrict__ x,
                                const float* __restrict__ emb,
                                const float* __restrict__ rel) {
    int b = blockIdx.x >> 4;
    int k = blockIdx.x & 15;
    __shared__ __align__(16) float so[LL * DD];   // o[b] (16KB)
    int tid = threadIdx.x;

    // gather embeddings for this batch
    for (int i = tid; i < LL * DD; i += 256) {
        int l = i >> 6;
        int d = i & 63;
        int tok = x[b * LL + l];
        so[i] = emb[tok * DD + d];
    }
    __syncthreads();

    if (k == 0) {
        for (int i = tid; i < LL * DD; i += 256) g_o[b * LL * DD + i] = so[i];
    }

    int d  = tid & 63;     // output dim
    int jg = tid >> 6;     // 0..3 j-group
    // load row d of M_k into registers
    float4 m[16];
    const float4* mrow = reinterpret_cast<const float4*>(rel + k * DD * DD + d * DD);
#pragma unroll
    for (int q = 0; q < 16; q++) m[q] = mrow[q];

    for (int jj = 0; jj < 16; jj++) {
        int j = jg * 16 + jj;
        const float4* orow = reinterpret_cast<const float4*>(so + j * DD);
        float acc = 0.f;
#pragma unroll
        for (int q = 0; q < 16; q++) {
            float4 ov = orow[q];
            acc += m[q].x * ov.x + m[q].y * ov.y + m[q].z * ov.z + m[q].w * ov.w;
        }
        g_v[(((b * RELN + k) * LL + j) * DD) + d] = acc;
    }
}

// ---------------- KB: scores + softmax + context + proj + GRU input proj -----
// grid = 256 blocks: b = blk>>6, i = blk&63; 64 threads
__global__ void kb_attn(const int* __restrict__ r,
                        const float* __restrict__ attW,
                        const float* __restrict__ attb,
                        const float* __restrict__ gWih,
                        const float* __restrict__ gbih) {
    int b = blockIdx.x >> 6;
    int i = blockIdx.x & 63;
    int tid = threadIdx.x;   // 64

    __shared__ float sob[LL][DD + 1];           // padded: conflict-free column reads
    __shared__ __align__(16) float soi[DD];
    __shared__ float sp[LL];
    __shared__ __align__(16) float sctx[DD];
    __shared__ __align__(16) float so2[DD];
    __shared__ float wmax[2], wsum[2];

    // load o[b]: thread tid loads column tid for all rows (coalesced per row)
    const float* ob = g_o + b * LL * DD;
    for (int jj = 0; jj < LL; jj++) sob[jj][tid] = ob[jj * DD + tid];
    __syncthreads();
    soi[tid] = sob[i][tid];
    __syncthreads();

    // score for j = tid
    int j = tid;
    int rj = r[(b * LL + i) * LL + j];
    float s;
    if (rj > 0) {
        const float4* vrow = reinterpret_cast<const float4*>(
            g_v + (((b * RELN + rj) * LL + j) * DD));
        const float4* oi4 = reinterpret_cast<const float4*>(soi);
        float acc = 0.f;
#pragma unroll
        for (int q = 0; q < 16; q++) {
            float4 v4 = vrow[q];
            float4 o4 = oi4[q];
            acc += v4.x * o4.x + v4.y * o4.y + v4.z * o4.z + v4.w * o4.w;
        }
        s = acc;
    } else {
        s = NEGV;
    }

    // softmax over 64 lanes (2 warps)
    float mx = s;
#pragma unroll
    for (int off = 16; off; off >>= 1) mx = fmaxf(mx, __shfl_xor_sync(0xFFFFFFFFu, mx, off));
    if ((tid & 31) == 0) wmax[tid >> 5] = mx;
    __syncthreads();
    mx = fmaxf(wmax[0], wmax[1]);
    float e = expf(s - mx);
    float ss = e;
#pragma unroll
    for (int off = 16; off; off >>= 1) ss += __shfl_xor_sync(0xFFFFFFFFu, ss, off);
    if ((tid & 31) == 0) wsum[tid >> 5] = ss;
    __syncthreads();
    float tot = wsum[0] + wsum[1];
    sp[tid] = e / tot;
    __syncthreads();

    // context: d = tid
    {
        float acc = 0.f;
        for (int jj = 0; jj < LL; jj++) acc += sp[jj] * sob[jj][tid];
        sctx[tid] = acc;
    }
    __syncthreads();

    // attention output projection: o2[d'] = ctx . attW[d',:] + attb[d']
    {
        const float4* wr = reinterpret_cast<const float4*>(attW + tid * DD);
        const float4* c4 = reinterpret_cast<const float4*>(sctx);
        float acc = attb[tid];
#pragma unroll
        for (int q = 0; q < 16; q++) {
            float4 w4 = wr[q];
            float4 cc = c4[q];
            acc += w4.x * cc.x + w4.y * cc.y + w4.z * cc.z + w4.w * cc.w;
        }
        so2[tid] = acc;
    }
    __syncthreads();

    // GRU input projection: gx[g] = o2 . gWih[g,:] + gbih[g], rows tid, tid+64, tid+128
    const float4* o24 = reinterpret_cast<const float4*>(so2);
    float* gxout = g_gx + (b * LL + i) * (3 * DD);
#pragma unroll
    for (int gset = 0; gset < 3; gset++) {
        int g = gset * DD + tid;
        const float4* wr = reinterpret_cast<const float4*>(gWih + g * DD);
        float acc = gbih[g];
#pragma unroll
        for (int q = 0; q < 16; q++) {
            float4 w4 = wr[q];
            float4 ov = o24[q];
            acc += w4.x * ov.x + w4.y * ov.y + w4.z * ov.z + w4.w * ov.w;
        }
        gxout[g] = acc;
    }
}

// ---------------- KC: serial GRU, one block per batch, 192 threads -----------
__global__ void kc_gru(const float* __restrict__ Whh,
                       const float* __restrict__ bhh) {
    int b = blockIdx.x;
    int k = threadIdx.x;   // 0..191

    __shared__ __align__(16) float sh[DD];
    __shared__ float sgh[3 * DD];

    // preload this thread's Whh row into registers
    float4 w[16];
    const float4* wr = reinterpret_cast<const float4*>(Whh + k * DD);
#pragma unroll
    for (int q = 0; q < 16; q++) w[q] = wr[q];
    float bk = bhh[k];

    if (k < DD) sh[k] = 0.f;
    __syncthreads();

    const float* gxb = g_gx + b * LL * (3 * DD);
    float* hout = g_hseq + b * LL * DD;

    for (int l = 0; l < LL; l++) {
        const float4* h4 = reinterpret_cast<const float4*>(sh);
        float acc = bk;
#pragma unroll
        for (int q = 0; q < 16; q++) {
            float4 hv = h4[q];
            acc += w[q].x * hv.x + w[q].y * hv.y + w[q].z * hv.z + w[q].w * hv.w;
        }
        sgh[k] = acc;
        __syncthreads();
        if (k < DD) {
            float hr = sgh[k];
            float hz = sgh[DD + k];
            float hn = sgh[2 * DD + k];
            float xr = gxb[l * 3 * DD + k];
            float xz = gxb[l * 3 * DD + DD + k];
            float xn = gxb[l * 3 * DD + 2 * DD + k];
            float rg = 1.f / (1.f + expf(-(xr + hr)));
            float zg = 1.f / (1.f + expf(-(xz + hz)));
            float ng = tanhf(xn + rg * hn);
            float hnew = (1.f - zg) * ng + zg * sh[k];
            sh[k] = hnew;
            hout[l * DD + k] = hnew;
        }
        __syncthreads();
    }
}

// ---------------- KD: output GRU + pooling + classifier + loss ---------------
__global__ void kd_final(const int* __restrict__ yv, const int* __restrict__ lv,
                         const float* __restrict__ oWih, const float* __restrict__ oWhh,
                         const float* __restrict__ obih, const float* __restrict__ obhh,
                         const float* __restrict__ W1, const float* __restrict__ b1,
                         const float* __restrict__ W2, const float* __restrict__ b2,
                         float* __restrict__ out, int out_size) {
    int tid = threadIdx.x;   // 256

    __shared__ float sga[BB][LL][3];
    __shared__ float sa[BB][LL];
    __shared__ float sgaw[BB][LL];
    __shared__ float sc[BB][DD];
    __shared__ float sh1[BB][DD / 2];
    __shared__ float slog[BB][2];
    __shared__ int smaxl;

    // out-GRU input projections: 768 dots of 64
    for (int t = tid; t < BB * LL * 3; t += 256) {
        int b = t / (LL * 3);
        int rem = t % (LL * 3);
        int l = rem / 3;
        int g = rem % 3;
        const float* orow = g_hseq + (b * LL + l) * DD;
        const float* wrow = oWih + g * DD;
        float acc = obih[g];
        for (int d = 0; d < DD; d++) acc += orow[d] * wrow[d];
        sga[b][l][g] = acc;
    }
    if (tid == 0) {
        int m = lv[0];
        for (int i = 1; i < BB; i++) m = max(m, lv[i]);
        smaxl = m + 1;
    }
    __syncthreads();

    // scalar GRU recurrence per batch
    if (tid < BB) {
        int b = tid;
        float h = 0.f;
        float w0 = oWhh[0], w1 = oWhh[1], w2 = oWhh[2];
        float c0 = obhh[0], c1 = obhh[1], c2 = obhh[2];
        for (int l = 0; l < LL; l++) {
            float hr = h * w0 + c0;
            float hz = h * w1 + c1;
            float hn = h * w2 + c2;
            float rg = 1.f / (1.f + expf(-(sga[b][l][0] + hr)));
            float zg = 1.f / (1.f + expf(-(sga[b][l][1] + hz)));
            float ng = tanhf(sga[b][l][2] + rg * hn);
            h = (1.f - zg) * ng + zg * h;
            sa[b][l] = h;
        }
        // masked softmax over L
        float mx = -1e30f;
        for (int l = 0; l < LL; l++) {
            float v = (l < smaxl) ? sa[b][l] : NEGV;
            sa[b][l] = v;
            if (v > mx) mx = v;
        }
        float sum = 0.f;
        for (int l = 0; l < LL; l++) {
            float e = expf(sa[b][l] - mx);
            sgaw[b][l] = e;
            sum += e;
        }
        float inv = 1.f / sum;
        for (int l = 0; l < LL; l++) sgaw[b][l] *= inv;
    }
    __syncthreads();

    // pooled context c[b][d]
    {
        int b = tid >> 6;
        int d = tid & 63;
        float acc = 0.f;
        for (int l = 0; l < LL; l++) acc += sgaw[b][l] * g_hseq[(b * LL + l) * DD + d];
        sc[b][d] = acc;
    }
    __syncthreads();

    // classifier layer 1 (ReLU)
    if (tid < BB * 32) {
        int b = tid >> 5;
        int m = tid & 31;
        const float* wr = W1 + m * DD;
        float acc = b1[m];
        for (int d = 0; d < DD; d++) acc += sc[b][d] * wr[d];
        sh1[b][m] = fmaxf(acc, 0.f);
    }
    __syncthreads();

    // classifier layer 2 (logits)
    if (tid < BB * 2) {
        int b = tid >> 1;
        int c2 = tid & 1;
        const float* wr = W2 + c2 * 32;
        float acc = b2[c2];
        for (int m = 0; m < 32; m++) acc += sh1[b][m] * wr[m];
        slog[b][c2] = acc;
    }
    __syncthreads();

    if (tid == 0) {
        float loss = 0.f;
        for (int b = 0; b < BB; b++) {
            float a0 = slog[b][0], a1 = slog[b][1];
            float mx = fmaxf(a0, a1);
            float e0 = expf(a0 - mx), e1 = expf(a1 - mx);
            float z = e0 + e1;
            if (2 * b < out_size)     out[2 * b]     = e0 / z;
            if (2 * b + 1 < out_size) out[2 * b + 1] = e1 / z;
            float chosen = (yv[b] == 0) ? a0 : a1;
            loss -= (chosen - mx - logf(z));
        }
        loss *= (1.f / BB);
        if (out_size > 8) out[8] = loss;
    }
    // defensively zero any extra tail elements
    for (int i = 9 + tid; i < out_size; i += 256) out[i] = 0.f;
}

// ---------------- launch ------------------------------------------------------
extern "C" void kernel_launch(void* const* d_in, const int* in_sizes, int n_in,
                              void* d_out, int out_size) {
    const int*   x    = (const int*)  d_in[0];
    const int*   y    = (const int*)  d_in[1];
    const int*   r    = (const int*)  d_in[2];
    const int*   l    = (const int*)  d_in[3];
    const float* emb  = (const float*)d_in[4];
    const float* rel  = (const float*)d_in[5];
    const float* attW = (const float*)d_in[6];
    const float* attb = (const float*)d_in[7];
    const float* gWih = (const float*)d_in[8];
    const float* gWhh = (const float*)d_in[9];
    const float* gbih = (const float*)d_in[10];
    const float* gbhh = (const float*)d_in[11];
    const float* oWih = (const float*)d_in[12];
    const float* oWhh = (const float*)d_in[13];
    const float* obih = (const float*)d_in[14];
    const float* obhh = (const float*)d_in[15];
    const float* W1   = (const float*)d_in[16];
    const float* b1   = (const float*)d_in[17];
    const float* W2   = (const float*)d_in[18];
    const float* b2   = (const float*)d_in[19];

    ka_embed_relmat<<<BB * RELN, 256>>>(x, emb, rel);
    kb_attn<<<BB * LL, 64>>>(r, attW, attb, gWih, gbih);
    kc_gru<<<BB, 192>>>(gWhh, gbhh);
    kd_final<<<1, 256>>>(y, l, oWih, oWhh, obih, obhh, W1, b1, W2, b2,
                         (float*)d_out, out_size);
}

// round 2
// speedup vs baseline: 1.3939x; 1.3939x over previous
#include <cuda_runtime.h>
#include <cuda_bf16.h>
#include <math.h>

// Problem constants
#define BB 4
#define LL 64
#define DD 64
#define RELN 16
#define NEGV (-1e9f)

// ---------------- fast math helpers ------------------------------------------
__device__ __forceinline__ float rcpa(float x) {
    float y; asm("rcp.approx.f32 %0, %1;" : "=f"(y) : "f"(x)); return y;
}
__device__ __forceinline__ float sigm(float x) {         // 1/(1+e^-x), ~1e-7 rel err
    return rcpa(1.f + __expf(-x));
}
__device__ __forceinline__ float tanha(float x) {        // 1 - 2/(e^2x+1), ~1e-7 rel err
    return 1.f - 2.f * rcpa(__expf(2.f * x) + 1.f);
}

// ---------------- packed f32x2 FMA helpers ------------------------------------
__device__ __forceinline__ void fma2(unsigned long long& d,
                                     unsigned long long a, unsigned long long b) {
    asm("fma.rn.f32x2 %0, %1, %2, %0;" : "+l"(d) : "l"(a), "l"(b));
}
__device__ __forceinline__ void unpack2(unsigned long long v, float& x, float& y) {
    asm("mov.b64 {%0,%1}, %2;" : "=f"(x), "=f"(y) : "l"(v));
}
// 64-float dot product via packed f32x2 FMAs, 4 independent accumulators.
// Both pointers must be 16B-aligned.
__device__ __forceinline__ float dot64(const ulonglong2* __restrict__ a,
                                       const ulonglong2* __restrict__ b) {
    unsigned long long a0 = 0ULL, a1 = 0ULL, a2 = 0ULL, a3 = 0ULL;
#pragma unroll
    for (int q = 0; q < 16; q += 2) {
        ulonglong2 x = a[q], y = b[q];
        ulonglong2 x2 = a[q + 1], y2 = b[q + 1];
        fma2(a0, x.x, y.x);  fma2(a1, x.y, y.y);
        fma2(a2, x2.x, y2.x); fma2(a3, x2.y, y2.y);
    }
    float s0, s1, s2, s3, s4, s5, s6, s7;
    unpack2(a0, s0, s1); unpack2(a1, s2, s3);
    unpack2(a2, s4, s5); unpack2(a3, s6, s7);
    return ((s0 + s1) + (s2 + s3)) + ((s4 + s5) + (s6 + s7));
}

// ---------------- scratch (__device__ globals; no allocation) ----------------
__device__ __align__(16) float g_o[BB * LL * DD];
__device__ __align__(16) float g_v[BB * RELN * LL * DD];
__device__ __align__(16) float g_gx[BB * LL * 3 * DD];
__device__ __align__(16) float g_hseq[BB * LL * DD];

// ---------------- KA: embedding gather + relation matvec precompute ----------
__global__ void ka_embed_relmat(const int* __restrict__ x,
                                const float* __restrict__ emb,
                                const float* __restrict__ rel) {
    int b = blockIdx.x >> 4;
    int k = blockIdx.x & 15;
    __shared__ __align__(16) float so[LL * DD];
    int tid = threadIdx.x;

    for (int i = tid; i < LL * DD; i += 256) {
        int l = i >> 6;
        int d = i & 63;
        int tok = x[b * LL + l];
        so[i] = emb[tok * DD + d];
    }
    __syncthreads();

    if (k == 0) {
        for (int i = tid; i < LL * DD; i += 256) g_o[b * LL * DD + i] = so[i];
    }

    int d  = tid & 63;
    int jg = tid >> 6;
    // row d of M_k in registers (packed)
    ulonglong2 m[16];
    const ulonglong2* mrow = reinterpret_cast<const ulonglong2*>(rel + k * DD * DD + d * DD);
#pragma unroll
    for (int q = 0; q < 16; q++) m[q] = mrow[q];

    for (int jj = 0; jj < 16; jj++) {
        int j = jg * 16 + jj;
        const ulonglong2* orow = reinterpret_cast<const ulonglong2*>(so + j * DD);
        unsigned long long a0 = 0ULL, a1 = 0ULL, a2 = 0ULL, a3 = 0ULL;
#pragma unroll
        for (int q = 0; q < 16; q += 2) {
            ulonglong2 ov = orow[q], ov2 = orow[q + 1];
            fma2(a0, m[q].x, ov.x);   fma2(a1, m[q].y, ov.y);
            fma2(a2, m[q + 1].x, ov2.x); fma2(a3, m[q + 1].y, ov2.y);
        }
        float s0, s1, s2, s3, s4, s5, s6, s7;
        unpack2(a0, s0, s1); unpack2(a1, s2, s3);
        unpack2(a2, s4, s5); unpack2(a3, s6, s7);
        g_v[(((b * RELN + k) * LL + j) * DD) + d] =
            ((s0 + s1) + (s2 + s3)) + ((s4 + s5) + (s6 + s7));
    }
}

// ---------------- KB: scores + softmax + context + proj + GRU input proj -----
__global__ void kb_attn(const int* __restrict__ r,
                        const float* __restrict__ attW,
                        const float* __restrict__ attb,
                        const float* __restrict__ gWih,
                        const float* __restrict__ gbih) {
    int b = blockIdx.x >> 6;
    int i = blockIdx.x & 63;
    int tid = threadIdx.x;   // 64

    __shared__ float sob[LL][DD + 1];
    __shared__ __align__(16) float soi[DD];
    __shared__ float sp[LL];
    __shared__ __align__(16) float sctx[DD];
    __shared__ __align__(16) float so2[DD];
    __shared__ float wmax[2], wsum[2];

    const float* ob = g_o + b * LL * DD;
    for (int jj = 0; jj < LL; jj++) sob[jj][tid] = ob[jj * DD + tid];
    __syncthreads();
    soi[tid] = sob[i][tid];
    __syncthreads();

    int j = tid;
    int rj = r[(b * LL + i) * LL + j];
    float s;
    if (rj > 0) {
        s = dot64(reinterpret_cast<const ulonglong2*>(
                      g_v + (((b * RELN + rj) * LL + j) * DD)),
                  reinterpret_cast<const ulonglong2*>(soi));
    } else {
        s = NEGV;
    }

    float mx = s;
#pragma unroll
    for (int off = 16; off; off >>= 1) mx = fmaxf(mx, __shfl_xor_sync(0xFFFFFFFFu, mx, off));
    if ((tid & 31) == 0) wmax[tid >> 5] = mx;
    __syncthreads();
    mx = fmaxf(wmax[0], wmax[1]);
    float e = __expf(s - mx);
    float ss = e;
#pragma unroll
    for (int off = 16; off; off >>= 1) ss += __shfl_xor_sync(0xFFFFFFFFu, ss, off);
    if ((tid & 31) == 0) wsum[tid >> 5] = ss;
    __syncthreads();
    float inv = rcpa(wsum[0] + wsum[1]);
    sp[tid] = e * inv;
    __syncthreads();

    {
        float acc = 0.f;
        for (int jj = 0; jj < LL; jj++) acc += sp[jj] * sob[jj][tid];
        sctx[tid] = acc;
    }
    __syncthreads();

    so2[tid] = attb[tid] +
               dot64(reinterpret_cast<const ulonglong2*>(attW + tid * DD),
                     reinterpret_cast<const ulonglong2*>(sctx));
    __syncthreads();

    float* gxout = g_gx + (b * LL + i) * (3 * DD);
#pragma unroll
    for (int gset = 0; gset < 3; gset++) {
        int g = gset * DD + tid;
        gxout[g] = gbih[g] +
                   dot64(reinterpret_cast<const ulonglong2*>(gWih + g * DD),
                         reinterpret_cast<const ulonglong2*>(so2));
    }
}

// ---------------- KC: serial GRU, one block per batch, 192 threads -----------
__global__ void kc_gru(const float* __restrict__ Whh,
                       const float* __restrict__ bhh) {
    int b = blockIdx.x;
    int k = threadIdx.x;   // 0..191

    __shared__ __align__(16) float sh[DD];
    __shared__ float sgh[3 * DD];

    // this thread's Whh row in registers (packed f32x2)
    ulonglong2 w[16];
    const ulonglong2* wr = reinterpret_cast<const ulonglong2*>(Whh + k * DD);
#pragma unroll
    for (int q = 0; q < 16; q++) w[q] = wr[q];
    float bk = bhh[k];

    if (k < DD) sh[k] = 0.f;
    __syncthreads();

    const float* gxb = g_gx + b * LL * (3 * DD);
    float* hout = g_hseq + b * LL * DD;

    // prefetch gx for l=0
    float xr = 0.f, xz = 0.f, xn = 0.f;
    if (k < DD) { xr = gxb[k]; xz = gxb[DD + k]; xn = gxb[2 * DD + k]; }

    for (int l = 0; l < LL; l++) {
        const ulonglong2* h2 = reinterpret_cast<const ulonglong2*>(sh);
        unsigned long long a0 = 0ULL, a1 = 0ULL, a2 = 0ULL, a3 = 0ULL;
#pragma unroll
        for (int q = 0; q < 16; q += 2) {
            ulonglong2 hA = h2[q], hB = h2[q + 1];
            fma2(a0, w[q].x, hA.x);     fma2(a1, w[q].y, hA.y);
            fma2(a2, w[q + 1].x, hB.x); fma2(a3, w[q + 1].y, hB.y);
        }
        float s0, s1, s2, s3, s4, s5, s6, s7;
        unpack2(a0, s0, s1); unpack2(a1, s2, s3);
        unpack2(a2, s4, s5); unpack2(a3, s6, s7);
        sgh[k] = bk + ((s0 + s1) + (s2 + s3)) + ((s4 + s5) + (s6 + s7));
        __syncthreads();
        if (k < DD) {
            float hr = sgh[k];
            float hz = sgh[DD + k];
            float hn = sgh[2 * DD + k];
            float rg = sigm(xr + hr);
            float zg = sigm(xz + hz);
            float ng = tanha(xn + rg * hn);
            float hnew = (1.f - zg) * ng + zg * sh[k];
            sh[k] = hnew;
            hout[l * DD + k] = hnew;
            if (l + 1 < LL) {   // prefetch next step's gx under barrier+matvec
                const float* nx = gxb + (l + 1) * 3 * DD;
                xr = nx[k]; xz = nx[DD + k]; xn = nx[2 * DD + k];
            }
        }
        __syncthreads();
    }
}

// ---------------- KD: output GRU + pooling + classifier + loss ---------------
__global__ void kd_final(const int* __restrict__ yv, const int* __restrict__ lv,
                         const float* __restrict__ oWih, const float* __restrict__ oWhh,
                         const float* __restrict__ obih, const float* __restrict__ obhh,
                         const float* __restrict__ W1, const float* __restrict__ b1,
                         const float* __restrict__ W2, const float* __restrict__ b2,
                         float* __restrict__ out, int out_size) {
    int tid = threadIdx.x;   // 256

    __shared__ float sga[BB][LL][3];
    __shared__ float sa[BB][LL];
    __shared__ float sgaw[BB][LL];
    __shared__ __align__(16) float sc[BB][DD];
    __shared__ float sh1[BB][DD / 2];
    __shared__ float slog[BB][2];
    __shared__ int smaxl;

    // out-GRU input projections (768 dots of 64)
    for (int t = tid; t < BB * LL * 3; t += 256) {
        int b = t / (LL * 3);
        int rem = t % (LL * 3);
        int l = rem / 3;
        int g = rem % 3;
        sga[b][l][g] = obih[g] +
            dot64(reinterpret_cast<const ulonglong2*>(g_hseq + (b * LL + l) * DD),
                  reinterpret_cast<const ulonglong2*>(oWih + g * DD));
    }
    if (tid == 0) {
        int m = lv[0];
        for (int i = 1; i < BB; i++) m = max(m, lv[i]);
        smaxl = m + 1;
    }
    __syncthreads();

    // scalar GRU recurrence per batch (serial but fast-math)
    if (tid < BB) {
        int b = tid;
        float h = 0.f;
        float w0 = oWhh[0], w1 = oWhh[1], w2 = oWhh[2];
        float c0 = obhh[0], c1 = obhh[1], c2 = obhh[2];
        for (int l = 0; l < LL; l++) {
            float rg = sigm(sga[b][l][0] + h * w0 + c0);
            float zg = sigm(sga[b][l][1] + h * w1 + c1);
            float ng = tanha(sga[b][l][2] + rg * (h * w2 + c2));
            h = (1.f - zg) * ng + zg * h;
            sa[b][l] = h;
        }
        float mx = -1e30f;
        for (int l = 0; l < LL; l++) {
            float v = (l < smaxl) ? sa[b][l] : NEGV;
            sa[b][l] = v;
            if (v > mx) mx = v;
        }
        float sum = 0.f;
        for (int l = 0; l < LL; l++) {
            float e = __expf(sa[b][l] - mx);
            sgaw[b][l] = e;
            sum += e;
        }
        float inv = rcpa(sum);
        for (int l = 0; l < LL; l++) sgaw[b][l] *= inv;
    }
    __syncthreads();

    // pooled context c[b][d]
    {
        int b = tid >> 6;
        int d = tid & 63;
        float acc = 0.f;
#pragma unroll 8
        for (int l = 0; l < LL; l++) acc += sgaw[b][l] * g_hseq[(b * LL + l) * DD + d];
        sc[b][d] = acc;
    }
    __syncthreads();

    // classifier layer 1 (ReLU)
    if (tid < BB * 32) {
        int b = tid >> 5;
        int m = tid & 31;
        float acc = b1[m] +
            dot64(reinterpret_cast<const ulonglong2*>(W1 + m * DD),
                  reinterpret_cast<const ulonglong2*>(sc[b]));
        sh1[b][m] = fmaxf(acc, 0.f);
    }
    __syncthreads();

    // classifier layer 2 (logits)
    if (tid < BB * 2) {
        int b = tid >> 1;
        int c2 = tid & 1;
        const float* wr = W2 + c2 * 32;
        float acc = b2[c2];
#pragma unroll
        for (int m = 0; m < 32; m++) acc += sh1[b][m] * wr[m];
        slog[b][c2] = acc;
    }
    __syncthreads();

    if (tid == 0) {
        float loss = 0.f;
        for (int b = 0; b < BB; b++) {
            float a0 = slog[b][0], a1 = slog[b][1];
            float mx = fmaxf(a0, a1);
            float e0 = __expf(a0 - mx), e1 = __expf(a1 - mx);
            float z = e0 + e1;
            float invz = rcpa(z);
            if (2 * b < out_size)     out[2 * b]     = e0 * invz;
            if (2 * b + 1 < out_size) out[2 * b + 1] = e1 * invz;
            float chosen = (yv[b] == 0) ? a0 : a1;
            loss -= (chosen - mx - __logf(z));
        }
        loss *= (1.f / BB);
        if (out_size > 8) out[8] = loss;
    }
    for (int i = 9 + tid; i < out_size; i += 256) out[i] = 0.f;
}

// ---------------- launch ------------------------------------------------------
extern "C" void kernel_launch(void* const* d_in, const int* in_sizes, int n_in,
                              void* d_out, int out_size) {
    const int*   x    = (const int*)  d_in[0];
    const int*   y    = (const int*)  d_in[1];
    const int*   r    = (const int*)  d_in[2];
    const int*   l    = (const int*)  d_in[3];
    const float* emb  = (const float*)d_in[4];
    const float* rel  = (const float*)d_in[5];
    const float* attW = (const float*)d_in[6];
    const float* attb = (const float*)d_in[7];
    const float* gWih = (const float*)d_in[8];
    const float* gWhh = (const float*)d_in[9];
    const float* gbih = (const float*)d_in[10];
    const float* gbhh = (const float*)d_in[11];
    const float* oWih = (const float*)d_in[12];
    const float* oWhh = (const float*)d_in[13];
    const float* obih = (const float*)d_in[14];
    const float* obhh = (const float*)d_in[15];
    const float* W1   = (const float*)d_in[16];
    const float* b1   = (const float*)d_in[17];
    const float* W2   = (const float*)d_in[18];
    const float* b2   = (const float*)d_in[19];

    ka_embed_relmat<<<BB * RELN, 256>>>(x, emb, rel);
    kb_attn<<<BB * LL, 64>>>(r, attW, attb, gWih, gbih);
    kc_gru<<<BB, 192>>>(gWhh, gbhh);
    kd_final<<<1, 256>>>(y, l, oWih, oWhh, obih, obhh, W1, b1, W2, b2,
                         (float*)d_out, out_size);
}

// round 3
// speedup vs baseline: 1.5688x; 1.1255x over previous
#include <cuda_runtime.h>
#include <cuda_bf16.h>
#include <math.h>

#define BB 4
#define LL 64
#define DD 64
#define RELN 16
#define NEGV (-1e9f)

// ---------------- fast math helpers ------------------------------------------
__device__ __forceinline__ float rcpa(float x) {
    float y; asm("rcp.approx.f32 %0, %1;" : "=f"(y) : "f"(x)); return y;
}
__device__ __forceinline__ float sigm(float x)  { return rcpa(1.f + __expf(-x)); }
__device__ __forceinline__ float tanha(float x) { return 1.f - 2.f * rcpa(__expf(2.f * x) + 1.f); }

// ---------------- packed f32x2 FMA helpers ------------------------------------
__device__ __forceinline__ void fma2(unsigned long long& d,
                                     unsigned long long a, unsigned long long b) {
    asm("fma.rn.f32x2 %0, %1, %2, %0;" : "+l"(d) : "l"(a), "l"(b));
}
__device__ __forceinline__ void unpack2(unsigned long long v, float& x, float& y) {
    asm("mov.b64 {%0,%1}, %2;" : "=f"(x), "=f"(y) : "l"(v));
}
__device__ __forceinline__ float dot64(const ulonglong2* __restrict__ a,
                                       const ulonglong2* __restrict__ b) {
    unsigned long long a0 = 0ULL, a1 = 0ULL, a2 = 0ULL, a3 = 0ULL;
#pragma unroll
    for (int q = 0; q < 16; q += 2) {
        ulonglong2 x = a[q], y = b[q];
        ulonglong2 x2 = a[q + 1], y2 = b[q + 1];
        fma2(a0, x.x, y.x);  fma2(a1, x.y, y.y);
        fma2(a2, x2.x, y2.x); fma2(a3, x2.y, y2.y);
    }
    float s0, s1, s2, s3, s4, s5, s6, s7;
    unpack2(a0, s0, s1); unpack2(a1, s2, s3);
    unpack2(a2, s4, s5); unpack2(a3, s6, s7);
    return ((s0 + s1) + (s2 + s3)) + ((s4 + s5) + (s6 + s7));
}

// ---------------- scratch ------------------------------------------------------
__device__ __align__(16) float g_o[BB * LL * DD];
__device__ __align__(16) float g_v[BB * RELN * LL * DD];
__device__ __align__(16) float g_gx[BB * LL * 3 * DD];
__device__ __align__(16) float g_logits[BB * 2];

// ---------------- KA: embedding gather + relation matvec precompute ----------
// grid = 128: b = blk>>5, k = (blk>>1)&15, half = blk&1; 256 threads
__global__ void ka_embed_relmat(const int* __restrict__ x,
                                const float* __restrict__ emb,
                                const float* __restrict__ rel) {
    int b    = blockIdx.x >> 5;
    int k    = (blockIdx.x >> 1) & 15;
    int half = blockIdx.x & 1;
    __shared__ __align__(16) float so[LL * DD];
    int tid = threadIdx.x;

    for (int i = tid; i < LL * DD; i += 256) {
        int l = i >> 6;
        int d = i & 63;
        int tok = x[b * LL + l];
        so[i] = emb[tok * DD + d];
    }
    __syncthreads();

    if (k == 0 && half == 0) {
        for (int i = tid; i < LL * DD; i += 256) g_o[b * LL * DD + i] = so[i];
    }

    int d  = tid & 63;
    int jg = tid >> 6;                      // 0..3
    ulonglong2 m[16];
    const ulonglong2* mrow = reinterpret_cast<const ulonglong2*>(rel + k * DD * DD + d * DD);
#pragma unroll
    for (int q = 0; q < 16; q++) m[q] = mrow[q];

    int jbase = half * 32 + jg * 8;
#pragma unroll
    for (int jj = 0; jj < 8; jj++) {
        int j = jbase + jj;
        const ulonglong2* orow = reinterpret_cast<const ulonglong2*>(so + j * DD);
        unsigned long long a0 = 0ULL, a1 = 0ULL, a2 = 0ULL, a3 = 0ULL;
#pragma unroll
        for (int q = 0; q < 16; q += 2) {
            ulonglong2 ov = orow[q], ov2 = orow[q + 1];
            fma2(a0, m[q].x, ov.x);      fma2(a1, m[q].y, ov.y);
            fma2(a2, m[q + 1].x, ov2.x); fma2(a3, m[q + 1].y, ov2.y);
        }
        float s0, s1, s2, s3, s4, s5, s6, s7;
        unpack2(a0, s0, s1); unpack2(a1, s2, s3);
        unpack2(a2, s4, s5); unpack2(a3, s6, s7);
        g_v[(((b * RELN + k) * LL + j) * DD) + d] =
            ((s0 + s1) + (s2 + s3)) + ((s4 + s5) + (s6 + s7));
    }
}

// ---------------- KB: scores + softmax + context + proj + GRU input proj -----
__global__ void kb_attn(const int* __restrict__ r,
                        const float* __restrict__ attW,
                        const float* __restrict__ attb,
                        const float* __restrict__ gWih,
                        const float* __restrict__ gbih) {
    int b = blockIdx.x >> 6;
    int i = blockIdx.x & 63;
    int tid = threadIdx.x;   // 64

    __shared__ float sob[LL][DD + 1];
    __shared__ __align__(16) float soi[DD];
    __shared__ float sp[LL];
    __shared__ __align__(16) float sctx[DD];
    __shared__ __align__(16) float so2[DD];
    __shared__ float wmax[2], wsum[2];

    const float* ob = g_o + b * LL * DD;
    for (int jj = 0; jj < LL; jj++) sob[jj][tid] = ob[jj * DD + tid];
    __syncthreads();
    soi[tid] = sob[i][tid];
    __syncthreads();

    int j = tid;
    int rj = r[(b * LL + i) * LL + j];
    float s;
    if (rj > 0) {
        s = dot64(reinterpret_cast<const ulonglong2*>(
                      g_v + (((b * RELN + rj) * LL + j) * DD)),
                  reinterpret_cast<const ulonglong2*>(soi));
    } else {
        s = NEGV;
    }

    float mx = s;
#pragma unroll
    for (int off = 16; off; off >>= 1) mx = fmaxf(mx, __shfl_xor_sync(0xFFFFFFFFu, mx, off));
    if ((tid & 31) == 0) wmax[tid >> 5] = mx;
    __syncthreads();
    mx = fmaxf(wmax[0], wmax[1]);
    float e = __expf(s - mx);
    float ss = e;
#pragma unroll
    for (int off = 16; off; off >>= 1) ss += __shfl_xor_sync(0xFFFFFFFFu, ss, off);
    if ((tid & 31) == 0) wsum[tid >> 5] = ss;
    __syncthreads();
    float inv = rcpa(wsum[0] + wsum[1]);
    sp[tid] = e * inv;
    __syncthreads();

    {
        float acc = 0.f;
        for (int jj = 0; jj < LL; jj++) acc += sp[jj] * sob[jj][tid];
        sctx[tid] = acc;
    }
    __syncthreads();

    so2[tid] = attb[tid] +
               dot64(reinterpret_cast<const ulonglong2*>(attW + tid * DD),
                     reinterpret_cast<const ulonglong2*>(sctx));
    __syncthreads();

    float* gxout = g_gx + (b * LL + i) * (3 * DD);
#pragma unroll
    for (int gset = 0; gset < 3; gset++) {
        int g = gset * DD + tid;
        gxout[g] = gbih[g] +
                   dot64(reinterpret_cast<const ulonglong2*>(gWih + g * DD),
                         reinterpret_cast<const ulonglong2*>(so2));
    }
}

// ---------------- KC: GRU + out-GRU + pooling + classifier (per batch) -------
// grid = 4 (one block per batch), 192 threads
__global__ void kc_fused(const float* __restrict__ Whh,
                         const float* __restrict__ bhh,
                         const int* __restrict__ lv,
                         const float* __restrict__ oWih, const float* __restrict__ oWhh,
                         const float* __restrict__ obih, const float* __restrict__ obhh,
                         const float* __restrict__ W1, const float* __restrict__ b1,
                         const float* __restrict__ W2, const float* __restrict__ b2) {
    int b = blockIdx.x;
    int k = threadIdx.x;   // 0..191

    __shared__ __align__(16) float sh[DD];
    __shared__ float sgh[3 * DD];
    __shared__ __align__(16) float shseq[LL][DD];   // full GRU output, stays on-chip
    __shared__ float sga[LL][3];
    __shared__ float sa[LL];
    __shared__ float sw_[LL];
    __shared__ __align__(16) float sc[DD];
    __shared__ __align__(16) float sh1[DD / 2];
    __shared__ float wmax[2], wsum[2];
    __shared__ int smaxl;

    // Whh row k in registers
    ulonglong2 w[16];
    const ulonglong2* wr = reinterpret_cast<const ulonglong2*>(Whh + k * DD);
#pragma unroll
    for (int q = 0; q < 16; q++) w[q] = wr[q];
    float bk = bhh[k];

    if (k < DD) sh[k] = 0.f;
    if (k == 0) {
        int m = lv[0];
#pragma unroll
        for (int i = 1; i < BB; i++) m = max(m, lv[i]);
        smaxl = m + 1;
    }
    __syncthreads();

    const float* gxb = g_gx + b * LL * (3 * DD);

    float xr = 0.f, xz = 0.f, xn = 0.f;
    if (k < DD) { xr = gxb[k]; xz = gxb[DD + k]; xn = gxb[2 * DD + k]; }

    // ---- main GRU: 64 serial steps ----
    for (int l = 0; l < LL; l++) {
        const ulonglong2* h2 = reinterpret_cast<const ulonglong2*>(sh);
        unsigned long long a0 = 0ULL, a1 = 0ULL, a2 = 0ULL, a3 = 0ULL;
#pragma unroll
        for (int q = 0; q < 16; q += 2) {
            ulonglong2 hA = h2[q], hB = h2[q + 1];
            fma2(a0, w[q].x, hA.x);     fma2(a1, w[q].y, hA.y);
            fma2(a2, w[q + 1].x, hB.x); fma2(a3, w[q + 1].y, hB.y);
        }
        float s0, s1, s2, s3, s4, s5, s6, s7;
        unpack2(a0, s0, s1); unpack2(a1, s2, s3);
        unpack2(a2, s4, s5); unpack2(a3, s6, s7);
        sgh[k] = bk + ((s0 + s1) + (s2 + s3)) + ((s4 + s5) + (s6 + s7));
        __syncthreads();
        if (k < DD) {
            float hr = sgh[k];
            float hz = sgh[DD + k];
            float hn = sgh[2 * DD + k];
            float rg = sigm(xr + hr);
            float zg = sigm(xz + hz);
            float ng = tanha(xn + rg * hn);
            float hnew = (1.f - zg) * ng + zg * sh[k];
            sh[k] = hnew;
            shseq[l][k] = hnew;
            if (l + 1 < LL) {
                const float* nx = gxb + (l + 1) * 3 * DD;
                xr = nx[k]; xz = nx[DD + k]; xn = nx[2 * DD + k];
            }
        }
        __syncthreads();
    }

    // ---- out-GRU input projections: 192 dots (thread = (g,l)) ----
    {
        int g = k >> 6;        // 0..2
        int l = k & 63;
        sga[l][g] = obih[g] +
            dot64(reinterpret_cast<const ulonglong2*>(shseq[l]),
                  reinterpret_cast<const ulonglong2*>(oWih + g * DD));
    }
    __syncthreads();

    // ---- scalar GRU recurrence (serial on thread 0) ----
    if (k == 0) {
        float h = 0.f;
        float w0 = oWhh[0], w1 = oWhh[1], w2 = oWhh[2];
        float c0 = obhh[0], c1 = obhh[1], c2 = obhh[2];
        for (int l = 0; l < LL; l++) {
            float rg = sigm(sga[l][0] + h * w0 + c0);
            float zg = sigm(sga[l][1] + h * w1 + c1);
            float ng = tanha(sga[l][2] + rg * (h * w2 + c2));
            h = (1.f - zg) * ng + zg * h;
            sa[l] = h;
        }
    }
    __syncthreads();

    // ---- masked softmax over L (threads 0..63, two warps) ----
    if (k < DD) {
        float v = (k < smaxl) ? sa[k] : NEGV;
        float mx = v;
#pragma unroll
        for (int off = 16; off; off >>= 1) mx = fmaxf(mx, __shfl_xor_sync(0xFFFFFFFFu, mx, off));
        if ((k & 31) == 0) wmax[k >> 5] = mx;
    }
    __syncthreads();
    if (k < DD) {
        float v = (k < smaxl) ? sa[k] : NEGV;
        float mx = fmaxf(wmax[0], wmax[1]);
        float e = __expf(v - mx);
        float ss = e;
#pragma unroll
        for (int off = 16; off; off >>= 1) ss += __shfl_xor_sync(0xFFFFFFFFu, ss, off);
        if ((k & 31) == 0) wsum[k >> 5] = ss;
        sw_[k] = e;
    }
    __syncthreads();

    // ---- pooled context c[d] (threads 0..63) ----
    if (k < DD) {
        float inv = rcpa(wsum[0] + wsum[1]);
        float acc = 0.f;
#pragma unroll 8
        for (int l = 0; l < LL; l++) acc += sw_[l] * shseq[l][k];
        sc[k] = acc * inv;
    }
    __syncthreads();

    // ---- classifier layer 1 (threads 0..31) ----
    if (k < 32) {
        float acc = b1[k] +
            dot64(reinterpret_cast<const ulonglong2*>(W1 + k * DD),
                  reinterpret_cast<const ulonglong2*>(sc));
        sh1[k] = fmaxf(acc, 0.f);
    }
    __syncthreads();

    // ---- classifier layer 2 -> logits (threads 0..1) ----
    if (k < 2) {
        const float* wr2 = W2 + k * 32;
        float acc = b2[k];
#pragma unroll
        for (int m = 0; m < 32; m++) acc += sh1[m] * wr2[m];
        g_logits[b * 2 + k] = acc;
    }
}

// ---------------- KD': tiny finisher ------------------------------------------
__global__ void kd_loss(const int* __restrict__ yv,
                        float* __restrict__ out, int out_size) {
    int tid = threadIdx.x;  // 32
    if (tid == 0) {
        float loss = 0.f;
#pragma unroll
        for (int b = 0; b < BB; b++) {
            float a0 = g_logits[2 * b], a1 = g_logits[2 * b + 1];
            float mx = fmaxf(a0, a1);
            float e0 = __expf(a0 - mx), e1 = __expf(a1 - mx);
            float z = e0 + e1;
            float invz = rcpa(z);
            if (2 * b < out_size)     out[2 * b]     = e0 * invz;
            if (2 * b + 1 < out_size) out[2 * b + 1] = e1 * invz;
            float chosen = (yv[b] == 0) ? a0 : a1;
            loss -= (chosen - mx - __logf(z));
        }
        loss *= (1.f / BB);
        if (out_size > 8) out[8] = loss;
    }
    for (int i = 9 + tid; i < out_size; i += 32) out[i] = 0.f;
}

// ---------------- launch ------------------------------------------------------
extern "C" void kernel_launch(void* const* d_in, const int* in_sizes, int n_in,
                              void* d_out, int out_size) {
    const int*   x    = (const int*)  d_in[0];
    const int*   y    = (const int*)  d_in[1];
    const int*   r    = (const int*)  d_in[2];
    const int*   l    = (const int*)  d_in[3];
    const float* emb  = (const float*)d_in[4];
    const float* rel  = (const float*)d_in[5];
    const float* attW = (const float*)d_in[6];
    const float* attb = (const float*)d_in[7];
    const float* gWih = (const float*)d_in[8];
    const float* gWhh = (const float*)d_in[9];
    const float* gbih = (const float*)d_in[10];
    const float* gbhh = (const float*)d_in[11];
    const float* oWih = (const float*)d_in[12];
    const float* oWhh = (const float*)d_in[13];
    const float* obih = (const float*)d_in[14];
    const float* obhh = (const float*)d_in[15];
    const float* W1   = (const float*)d_in[16];
    const float* b1   = (const float*)d_in[17];
    const float* W2   = (const float*)d_in[18];
    const float* b2   = (const float*)d_in[19];

    ka_embed_relmat<<<BB * RELN * 2, 256>>>(x, emb, rel);
    kb_attn<<<BB * LL, 64>>>(r, attW, attb, gWih, gbih);
    kc_fused<<<BB, 192>>>(gWhh, gbhh, l, oWih, oWhh, obih, obhh, W1, b1, W2, b2);
    kd_loss<<<1, 32>>>(y, (float*)d_out, out_size);
}